// round 14
// baseline (speedup 1.0000x reference)
#include <cuda_runtime.h>
#include <cuda_bf16.h>

// Gemma4VisionPooler: 2x2 segment-mean pool (B=16, L=4096 -> 1024, H=1152) * sqrt(H)
// R9: R7 structure (best reproduced: 63.8us) + PDL overlap.
//   - scatter_kernel: one block per batch; staged decode in smem; all position
//     reads in-bounds for both int32/int64 layouts.
//   - pool_kernel: byte-identical data path (56.6us @ 6.2TB/s = roofline),
//     launched with programmatic stream serialization; performs
//     cudaGridDependencySynchronize() before consuming scatter's output, so
//     its 16384-block ramp-up overlaps scatter's execution.

#define BATCH  16
#define LIN    4096
#define HID    1152
#define OUTLEN 1024
#define KPOOL  2          // sqrt(LIN/OUTLEN)
#define SLOTS  4          // k^2 rows per segment
#define H4     (HID / 4)  // 288 float4 per row
#define NSEG   (BATCH * OUTLEN)
#define STHREADS 1024

// Scratch (allocation-free rule: __device__ globals)
__device__ int  g_cnt[NSEG];    // 1 if any row maps to segment -> mask
__device__ int  g_vcnt[NSEG];   // valid (non-padded) slot cursor
__device__ int4 g_idx4[NSEG];   // packed absolute row ids, -1 = empty

// ---------------------------------------------------------------------------
// Fused index build. One block per batch, 1024 threads.
// All reads stay within the int32-pair span [b*L*2, (b+1)*L*2), valid for BOTH
// dtypes; int64-view words 4l..4l+3 are only indexed AFTER dtype is known.
// ---------------------------------------------------------------------------
__global__ void __launch_bounds__(STHREADS) scatter_kernel(
    const int* __restrict__ p32,
    const unsigned char* __restrict__ pad)
{
    const int b   = blockIdx.x;
    const int tid = threadIdx.x;

    __shared__ int sx[LIN];
    __shared__ int sy[LIN];
    __shared__ int smax;
    __shared__ int s_is32;
    if (tid == 0) { smax = 0; s_is32 = 0; }

    // reset this batch's scratch region (exclusively owned by this block)
    for (int s = tid; s < OUTLEN; s += STHREADS) {
        const int bs = b * OUTLEN + s;
        g_cnt[bs]  = 0;
        g_vcnt[bs] = 0;
        g_idx4[bs] = make_int4(-1, -1, -1, -1);
    }
    __syncthreads();

    // dtype detect (int32 view, always in-bounds): int64 layout's odd words
    // are high words (0/-1); int32 layout's odd words are y coords (> 0 somewhere).
    {
        int found = 0;
        const int* base = p32 + (long long)b * LIN * 2;
        for (int i = tid * 2 + 1; i < LIN * 2; i += STHREADS * 2)
            if (base[i] > 0) found = 1;
        if (__syncthreads_or(found) && tid == 0) s_is32 = 1;
    }
    __syncthreads();
    const int is32 = s_is32;

    // decode positions once into shared, accumulate max clamped x
    int lmax = 0;
    for (int l = tid; l < LIN; l += STHREADS) {
        int xi, yi;
        if (is32) {
            const long long w = ((long long)b * LIN + l) * 2;
            xi = p32[w + 0];
            yi = p32[w + 1];
        } else {
            const long long w = ((long long)b * LIN + l) * 4;
            int xlo = p32[w + 0], xhi = p32[w + 1];
            int ylo = p32[w + 2], yhi = p32[w + 3];
            xi = (xhi < 0) ? -1 : xlo;
            yi = (yhi < 0) ? -1 : ylo;
        }
        if (xi < 0) xi = 0;
        if (yi < 0) yi = 0;
        sx[l] = xi;
        sy[l] = yi;
        lmax = max(lmax, xi);
    }
    atomicMax(&smax, lmax);   // shared-mem atomic: cheap
    __syncthreads();
    const int wseg = (smax + 1) / KPOOL;

    // scatter row ids into segment slot lists (16K distinct atomic addresses)
    for (int l = tid; l < LIN; l += STHREADS) {
        int seg = sx[l] / KPOOL + wseg * (sy[l] / KPOOL);
        if (seg < 0) seg = 0;
        if (seg >= OUTLEN) seg = OUTLEN - 1;   // never corrupt scratch
        const int bs = b * OUTLEN + seg;

        g_cnt[bs] = 1;                         // racing stores of 1: benign

        if (!pad[(long long)b * LIN + l]) {    // only non-padded rows contribute
            int slot = atomicAdd(&g_vcnt[bs], 1);
            if (slot < SLOTS)
                ((int*)&g_idx4[bs])[slot] = b * LIN + l;  // absolute row id
        }
    }
}

// ---------------------------------------------------------------------------
// Gather + mean + scale. One block per (batch, segment), 288 threads, each
// thread owns one float4 column. Launched with PDL: blocks may start while
// scatter is still running; the grid-dependency sync below orders every read
// of scatter's output after scatter completion.
// ---------------------------------------------------------------------------
__global__ void __launch_bounds__(H4) pool_kernel(
    const float4* __restrict__ in,
    float4* __restrict__ out,
    float* __restrict__ mask_out)
{
    const int bs  = blockIdx.x;          // b * OUTLEN + seg
    const int tid = threadIdx.x;

    // wait for scatter_kernel (PDL upstream) before consuming its output
    cudaGridDependencySynchronize();

    const int4 idx = g_idx4[bs];         // one LDG.128, uniform across block

    float4 acc = make_float4(0.f, 0.f, 0.f, 0.f);
    float4 v0, v1, v2, v3;
    const bool p0 = idx.x >= 0, p1 = idx.y >= 0, p2 = idx.z >= 0, p3 = idx.w >= 0;
    if (p0) v0 = __ldcs(&in[(long long)idx.x * H4 + tid]);
    if (p1) v1 = __ldcs(&in[(long long)idx.y * H4 + tid]);
    if (p2) v2 = __ldcs(&in[(long long)idx.z * H4 + tid]);
    if (p3) v3 = __ldcs(&in[(long long)idx.w * H4 + tid]);
    if (p0) { acc.x += v0.x; acc.y += v0.y; acc.z += v0.z; acc.w += v0.w; }
    if (p1) { acc.x += v1.x; acc.y += v1.y; acc.z += v1.z; acc.w += v1.w; }
    if (p2) { acc.x += v2.x; acc.y += v2.y; acc.z += v2.z; acc.w += v2.w; }
    if (p3) { acc.x += v3.x; acc.y += v3.y; acc.z += v3.z; acc.w += v3.w; }

    // pooled = sum / k^2, then * sqrt(H) :  sqrt(1152)/4
    const float SCALE = 8.4852813742385702928f;
    acc.x *= SCALE; acc.y *= SCALE; acc.z *= SCALE; acc.w *= SCALE;

    __stcs(&out[(long long)bs * H4 + tid], acc);

    if (mask_out != nullptr && tid == 0)
        mask_out[bs] = (g_cnt[bs] > 0) ? 1.0f : 0.0f;
}

// ---------------------------------------------------------------------------
extern "C" void kernel_launch(void* const* d_in, const int* in_sizes, int n_in,
                              void* d_out, int out_size)
{
    const float*         hs  = (const float*)d_in[0];          // [B, L, H] f32
    const int*           pos = (const int*)d_in[1];            // [B, L, 2] i32 or i64
    const unsigned char* pad = (const unsigned char*)d_in[2];  // [B, L] bool

    float* out = (float*)d_out;

    const long long hs_elems = (long long)BATCH * OUTLEN * HID;
    float* mask_out = nullptr;
    if ((long long)out_size >= hs_elems + (long long)BATCH * OUTLEN)
        mask_out = out + hs_elems;

    scatter_kernel<<<BATCH, STHREADS>>>(pos, pad);

    // PDL launch of pool_kernel: overlap its grid ramp-up with scatter's tail.
    cudaLaunchConfig_t cfg = {};
    cfg.gridDim  = dim3(NSEG, 1, 1);
    cfg.blockDim = dim3(H4, 1, 1);
    cfg.dynamicSmemBytes = 0;
    cfg.stream = 0;
    cudaLaunchAttribute attrs[1];
    attrs[0].id = cudaLaunchAttributeProgrammaticStreamSerialization;
    attrs[0].val.programmaticStreamSerializationAllowed = 1;
    cfg.attrs = attrs;
    cfg.numAttrs = 1;
    cudaLaunchKernelEx(&cfg, pool_kernel,
                       (const float4*)hs, (float4*)out, mask_out);
}

// round 15
// speedup vs baseline: 1.0338x; 1.0338x over previous
#include <cuda_runtime.h>
#include <cuda_bf16.h>

// Gemma4VisionPooler: 2x2 segment-mean pool (B=16, L=4096 -> 1024, H=1152) * sqrt(H)
// FINAL (pinned R7): best reproduced result, 63.8us.
//   scatter_kernel (~4.5us): one block per batch; resets its own scratch,
//     detects position dtype (int32 vs int64; all reads in-bounds for both),
//     computes per-batch max_x, builds packed int4 gather lists (padding
//     filtered here; g_cnt mask via benign racing stores).
//   pool_kernel (56.6us @ 6.2TB/s DRAM = mixed-stream HBM roofline for the
//     irreducible 378MB): one block per (batch,segment), one LDG.128 of the
//     packed index, 4 independent predicated streaming float4 loads, one
//     coalesced streaming store.
// Rejected by measurement: wide-grid spin-barrier scatter (neutral, R8),
// PDL overlap (regression from dependency-wait SM contention, R9),
// scatter atomics on hot addresses (catastrophic L2-atomic serialization, R3).

#define BATCH  16
#define LIN    4096
#define HID    1152
#define OUTLEN 1024
#define KPOOL  2          // sqrt(LIN/OUTLEN)
#define SLOTS  4          // k^2 rows per segment
#define H4     (HID / 4)  // 288 float4 per row
#define NSEG   (BATCH * OUTLEN)
#define STHREADS 1024

// Scratch (allocation-free rule: __device__ globals)
__device__ int  g_cnt[NSEG];    // 1 if any row maps to segment -> mask
__device__ int  g_vcnt[NSEG];   // valid (non-padded) slot cursor
__device__ int4 g_idx4[NSEG];   // packed absolute row ids, -1 = empty

// ---------------------------------------------------------------------------
// Fused index build. One block per batch, 1024 threads.
// All reads stay within the int32-pair span [b*L*2, (b+1)*L*2), valid for BOTH
// dtypes; int64-view words 4l..4l+3 are only indexed AFTER dtype is known.
// ---------------------------------------------------------------------------
__global__ void __launch_bounds__(STHREADS) scatter_kernel(
    const int* __restrict__ p32,
    const unsigned char* __restrict__ pad)
{
    const int b   = blockIdx.x;
    const int tid = threadIdx.x;

    __shared__ int sx[LIN];
    __shared__ int sy[LIN];
    __shared__ int smax;
    __shared__ int s_is32;
    if (tid == 0) { smax = 0; s_is32 = 0; }

    // reset this batch's scratch region (exclusively owned by this block)
    for (int s = tid; s < OUTLEN; s += STHREADS) {
        const int bs = b * OUTLEN + s;
        g_cnt[bs]  = 0;
        g_vcnt[bs] = 0;
        g_idx4[bs] = make_int4(-1, -1, -1, -1);
    }
    __syncthreads();

    // dtype detect (int32 view, always in-bounds): int64 layout's odd words
    // are high words (0/-1); int32 layout's odd words are y coords (>0 somewhere).
    {
        int found = 0;
        const int* base = p32 + (long long)b * LIN * 2;
        for (int i = tid * 2 + 1; i < LIN * 2; i += STHREADS * 2)
            if (base[i] > 0) found = 1;
        if (__syncthreads_or(found) && tid == 0) s_is32 = 1;
    }
    __syncthreads();
    const int is32 = s_is32;

    // decode positions once into shared, accumulate max clamped x
    int lmax = 0;
    for (int l = tid; l < LIN; l += STHREADS) {
        int xi, yi;
        if (is32) {
            const long long w = ((long long)b * LIN + l) * 2;
            xi = p32[w + 0];
            yi = p32[w + 1];
        } else {
            const long long w = ((long long)b * LIN + l) * 4;
            int xlo = p32[w + 0], xhi = p32[w + 1];
            int ylo = p32[w + 2], yhi = p32[w + 3];
            xi = (xhi < 0) ? -1 : xlo;
            yi = (yhi < 0) ? -1 : ylo;
        }
        if (xi < 0) xi = 0;
        if (yi < 0) yi = 0;
        sx[l] = xi;
        sy[l] = yi;
        lmax = max(lmax, xi);
    }
    atomicMax(&smax, lmax);   // shared-mem atomic: cheap
    __syncthreads();
    const int wseg = (smax + 1) / KPOOL;

    // scatter row ids into segment slot lists (16K distinct atomic addresses)
    for (int l = tid; l < LIN; l += STHREADS) {
        int seg = sx[l] / KPOOL + wseg * (sy[l] / KPOOL);
        if (seg < 0) seg = 0;
        if (seg >= OUTLEN) seg = OUTLEN - 1;   // never corrupt scratch
        const int bs = b * OUTLEN + seg;

        g_cnt[bs] = 1;                         // racing stores of 1: benign

        if (!pad[(long long)b * LIN + l]) {    // only non-padded rows contribute
            int slot = atomicAdd(&g_vcnt[bs], 1);
            if (slot < SLOTS)
                ((int*)&g_idx4[bs])[slot] = b * LIN + l;  // absolute row id
        }
    }
}

// ---------------------------------------------------------------------------
// Gather + mean + scale. One block per (batch, segment), 288 threads, each
// thread owns one float4 column. Single LDG.128 of the packed index, then 4
// independent predicated streaming loads. At HBM roofline.
// ---------------------------------------------------------------------------
__global__ void __launch_bounds__(H4) pool_kernel(
    const float4* __restrict__ in,
    float4* __restrict__ out,
    float* __restrict__ mask_out)
{
    const int bs  = blockIdx.x;          // b * OUTLEN + seg
    const int tid = threadIdx.x;

    const int4 idx = g_idx4[bs];         // one LDG.128, uniform across block

    float4 acc = make_float4(0.f, 0.f, 0.f, 0.f);
    float4 v0, v1, v2, v3;
    const bool p0 = idx.x >= 0, p1 = idx.y >= 0, p2 = idx.z >= 0, p3 = idx.w >= 0;
    if (p0) v0 = __ldcs(&in[(long long)idx.x * H4 + tid]);
    if (p1) v1 = __ldcs(&in[(long long)idx.y * H4 + tid]);
    if (p2) v2 = __ldcs(&in[(long long)idx.z * H4 + tid]);
    if (p3) v3 = __ldcs(&in[(long long)idx.w * H4 + tid]);
    if (p0) { acc.x += v0.x; acc.y += v0.y; acc.z += v0.z; acc.w += v0.w; }
    if (p1) { acc.x += v1.x; acc.y += v1.y; acc.z += v1.z; acc.w += v1.w; }
    if (p2) { acc.x += v2.x; acc.y += v2.y; acc.z += v2.z; acc.w += v2.w; }
    if (p3) { acc.x += v3.x; acc.y += v3.y; acc.z += v3.z; acc.w += v3.w; }

    // pooled = sum / k^2, then * sqrt(H) :  sqrt(1152)/4
    const float SCALE = 8.4852813742385702928f;
    acc.x *= SCALE; acc.y *= SCALE; acc.z *= SCALE; acc.w *= SCALE;

    __stcs(&out[(long long)bs * H4 + tid], acc);

    if (mask_out != nullptr && tid == 0)
        mask_out[bs] = (g_cnt[bs] > 0) ? 1.0f : 0.0f;
}

// ---------------------------------------------------------------------------
extern "C" void kernel_launch(void* const* d_in, const int* in_sizes, int n_in,
                              void* d_out, int out_size)
{
    const float*         hs  = (const float*)d_in[0];          // [B, L, H] f32
    const int*           pos = (const int*)d_in[1];            // [B, L, 2] i32 or i64
    const unsigned char* pad = (const unsigned char*)d_in[2];  // [B, L] bool

    float* out = (float*)d_out;

    const long long hs_elems = (long long)BATCH * OUTLEN * HID;
    float* mask_out = nullptr;
    if ((long long)out_size >= hs_elems + (long long)BATCH * OUTLEN)
        mask_out = out + hs_elems;

    scatter_kernel<<<BATCH, STHREADS>>>(pos, pad);
    pool_kernel<<<NSEG, H4>>>((const float4*)hs, (float4*)out, mask_out);
}

// round 17
// speedup vs baseline: 1.1072x; 1.0710x over previous
#include <cuda_runtime.h>
#include <cuda_bf16.h>

// Gemma4VisionPooler: 2x2 segment-mean pool (B=16, L=4096 -> 1024, H=1152) * sqrt(H)
// R11: pool kernel processes TWO segments per block (grid 8192 x 288) with all
// 8 gather loads issued back-to-back -> per-thread MLP 4 -> 8. Purpose: keep
// HBM saturated on slow DVFS draws where the 4-load version exposes latency
// (observed: identical binary swings 56.6us@6.2TB/s .. 60.5us@5.8TB/s).
// Scatter kernel unchanged from the pinned R7 version.

#define BATCH  16
#define LIN    4096
#define HID    1152
#define OUTLEN 1024
#define KPOOL  2          // sqrt(LIN/OUTLEN)
#define SLOTS  4          // k^2 rows per segment
#define H4     (HID / 4)  // 288 float4 per row
#define NSEG   (BATCH * OUTLEN)
#define STHREADS 1024

// Scratch (allocation-free rule: __device__ globals)
__device__ int  g_cnt[NSEG];    // 1 if any row maps to segment -> mask
__device__ int  g_vcnt[NSEG];   // valid (non-padded) slot cursor
__device__ int4 g_idx4[NSEG];   // packed absolute row ids, -1 = empty

// ---------------------------------------------------------------------------
// Fused index build. One block per batch, 1024 threads. (pinned R7 version)
// All reads stay within the int32-pair span [b*L*2, (b+1)*L*2), valid for BOTH
// dtypes; int64-view words 4l..4l+3 are only indexed AFTER dtype is known.
// ---------------------------------------------------------------------------
__global__ void __launch_bounds__(STHREADS) scatter_kernel(
    const int* __restrict__ p32,
    const unsigned char* __restrict__ pad)
{
    const int b   = blockIdx.x;
    const int tid = threadIdx.x;

    __shared__ int sx[LIN];
    __shared__ int sy[LIN];
    __shared__ int smax;
    __shared__ int s_is32;
    if (tid == 0) { smax = 0; s_is32 = 0; }

    // reset this batch's scratch region (exclusively owned by this block)
    for (int s = tid; s < OUTLEN; s += STHREADS) {
        const int bs = b * OUTLEN + s;
        g_cnt[bs]  = 0;
        g_vcnt[bs] = 0;
        g_idx4[bs] = make_int4(-1, -1, -1, -1);
    }
    __syncthreads();

    // dtype detect (int32 view, always in-bounds): int64 layout's odd words
    // are high words (0/-1); int32 layout's odd words are y coords (>0 somewhere).
    {
        int found = 0;
        const int* base = p32 + (long long)b * LIN * 2;
        for (int i = tid * 2 + 1; i < LIN * 2; i += STHREADS * 2)
            if (base[i] > 0) found = 1;
        if (__syncthreads_or(found) && tid == 0) s_is32 = 1;
    }
    __syncthreads();
    const int is32 = s_is32;

    // decode positions once into shared, accumulate max clamped x
    int lmax = 0;
    for (int l = tid; l < LIN; l += STHREADS) {
        int xi, yi;
        if (is32) {
            const long long w = ((long long)b * LIN + l) * 2;
            xi = p32[w + 0];
            yi = p32[w + 1];
        } else {
            const long long w = ((long long)b * LIN + l) * 4;
            int xlo = p32[w + 0], xhi = p32[w + 1];
            int ylo = p32[w + 2], yhi = p32[w + 3];
            xi = (xhi < 0) ? -1 : xlo;
            yi = (yhi < 0) ? -1 : ylo;
        }
        if (xi < 0) xi = 0;
        if (yi < 0) yi = 0;
        sx[l] = xi;
        sy[l] = yi;
        lmax = max(lmax, xi);
    }
    atomicMax(&smax, lmax);   // shared-mem atomic: cheap
    __syncthreads();
    const int wseg = (smax + 1) / KPOOL;

    // scatter row ids into segment slot lists (16K distinct atomic addresses)
    for (int l = tid; l < LIN; l += STHREADS) {
        int seg = sx[l] / KPOOL + wseg * (sy[l] / KPOOL);
        if (seg < 0) seg = 0;
        if (seg >= OUTLEN) seg = OUTLEN - 1;   // never corrupt scratch
        const int bs = b * OUTLEN + seg;

        g_cnt[bs] = 1;                         // racing stores of 1: benign

        if (!pad[(long long)b * LIN + l]) {    // only non-padded rows contribute
            int slot = atomicAdd(&g_vcnt[bs], 1);
            if (slot < SLOTS)
                ((int*)&g_idx4[bs])[slot] = b * LIN + l;  // absolute row id
        }
    }
}

// ---------------------------------------------------------------------------
// Gather + mean + scale, two segments per block. 288 threads; thread t owns
// float4 column t of BOTH segments. 8 independent predicated streaming loads
// issued before any accumulation (MLP=8), then two coalesced streaming stores.
// ---------------------------------------------------------------------------
__global__ void __launch_bounds__(H4) pool_kernel(
    const float4* __restrict__ in,
    float4* __restrict__ out,
    float* __restrict__ mask_out)
{
    const int bs0 = blockIdx.x * 2;      // first segment (b*OUTLEN+seg)
    const int bs1 = bs0 + 1;             // second segment (same batch: OUTLEN even)
    const int tid = threadIdx.x;

    const int4 ia = g_idx4[bs0];         // two uniform LDG.128s
    const int4 ib = g_idx4[bs1];

    float4 a0, a1, a2, a3, b0, b1, b2, b3;
    const bool pa0 = ia.x >= 0, pa1 = ia.y >= 0, pa2 = ia.z >= 0, pa3 = ia.w >= 0;
    const bool pb0 = ib.x >= 0, pb1 = ib.y >= 0, pb2 = ib.z >= 0, pb3 = ib.w >= 0;

    // all 8 loads in flight before any use
    if (pa0) a0 = __ldcs(&in[(long long)ia.x * H4 + tid]);
    if (pa1) a1 = __ldcs(&in[(long long)ia.y * H4 + tid]);
    if (pa2) a2 = __ldcs(&in[(long long)ia.z * H4 + tid]);
    if (pa3) a3 = __ldcs(&in[(long long)ia.w * H4 + tid]);
    if (pb0) b0 = __ldcs(&in[(long long)ib.x * H4 + tid]);
    if (pb1) b1 = __ldcs(&in[(long long)ib.y * H4 + tid]);
    if (pb2) b2 = __ldcs(&in[(long long)ib.z * H4 + tid]);
    if (pb3) b3 = __ldcs(&in[(long long)ib.w * H4 + tid]);

    float4 accA = make_float4(0.f, 0.f, 0.f, 0.f);
    float4 accB = make_float4(0.f, 0.f, 0.f, 0.f);
    if (pa0) { accA.x += a0.x; accA.y += a0.y; accA.z += a0.z; accA.w += a0.w; }
    if (pa1) { accA.x += a1.x; accA.y += a1.y; accA.z += a1.z; accA.w += a1.w; }
    if (pa2) { accA.x += a2.x; accA.y += a2.y; accA.z += a2.z; accA.w += a2.w; }
    if (pa3) { accA.x += a3.x; accA.y += a3.y; accA.z += a3.z; accA.w += a3.w; }
    if (pb0) { accB.x += b0.x; accB.y += b0.y; accB.z += b0.z; accB.w += b0.w; }
    if (pb1) { accB.x += b1.x; accB.y += b1.y; accB.z += b1.z; accB.w += b1.w; }
    if (pb2) { accB.x += b2.x; accB.y += b2.y; accB.z += b2.z; accB.w += b2.w; }
    if (pb3) { accB.x += b3.x; accB.y += b3.y; accB.z += b3.z; accB.w += b3.w; }

    // pooled = sum / k^2, then * sqrt(H) :  sqrt(1152)/4
    const float SCALE = 8.4852813742385702928f;
    accA.x *= SCALE; accA.y *= SCALE; accA.z *= SCALE; accA.w *= SCALE;
    accB.x *= SCALE; accB.y *= SCALE; accB.z *= SCALE; accB.w *= SCALE;

    __stcs(&out[(long long)bs0 * H4 + tid], accA);
    __stcs(&out[(long long)bs1 * H4 + tid], accB);

    if (mask_out != nullptr && tid == 0) {
        mask_out[bs0] = (g_cnt[bs0] > 0) ? 1.0f : 0.0f;
        mask_out[bs1] = (g_cnt[bs1] > 0) ? 1.0f : 0.0f;
    }
}

// ---------------------------------------------------------------------------
extern "C" void kernel_launch(void* const* d_in, const int* in_sizes, int n_in,
                              void* d_out, int out_size)
{
    const float*         hs  = (const float*)d_in[0];          // [B, L, H] f32
    const int*           pos = (const int*)d_in[1];            // [B, L, 2] i32 or i64
    const unsigned char* pad = (const unsigned char*)d_in[2];  // [B, L] bool

    float* out = (float*)d_out;

    const long long hs_elems = (long long)BATCH * OUTLEN * HID;
    float* mask_out = nullptr;
    if ((long long)out_size >= hs_elems + (long long)BATCH * OUTLEN)
        mask_out = out + hs_elems;

    scatter_kernel<<<BATCH, STHREADS>>>(pos, pad);
    pool_kernel<<<NSEG / 2, H4>>>((const float4*)hs, (float4*)out, mask_out);
}